// round 15
// baseline (speedup 1.0000x reference)
#include <cuda_runtime.h>
#include <math.h>

#define Bc 32
#define Ac 5
#define Hc 64
#define Wc 64
#define HWc 4096
#define Gc 16
#define NCLS 80
#define CHc 86
#define SPLIT 16
#define NBLK (Bc * Ac * SPLIT)   // 2560 blocks x 64 threads, 1 float4/thread

// 32 spread accumulator slots: x=conf sq-sum, y=coord, z=cls nll, w=theta.
// Zero at module load; finalize kernel resets after reading (graph-replay safe).
__device__ float4 g_slot[32];

__constant__ float c_aw[5] = {1.3221f, 3.19275f, 5.05587f, 9.47112f, 11.2364f};
__constant__ float c_ah[5] = {1.73145f, 4.00944f, 8.09892f, 4.84053f, 10.0071f};
__constant__ float c_aa[5] = {0.0f, 0.3927f, 0.7854f, 1.1781f, 1.5708f};

__device__ __forceinline__ float sigf(float x) {
    return __fdividef(1.0f, 1.0f + __expf(-x));
}

__global__ __launch_bounds__(64) void k_main(const float* __restrict__ out,
                                             const float* __restrict__ gtb,
                                             const int* __restrict__ gtc) {
    const int tid  = threadIdx.x;
    const int lane = tid & 31;
    const int wid  = tid >> 5;          // 0 or 1
    const int bid  = blockIdx.x;

    // ---- per-gt inputs first: start the dependent chain early (blocks 0..511, warp 0) ----
    const bool has_gt = (bid < Bc * Gc) && (wid == 0);
    float bx0 = 0.f, bx1 = 0.f, bx2 = 0.f, bx3 = 0.f, bx4 = 0.f;
    int cls = 0;
    if (has_gt) {
        const float* box = gtb + (size_t)bid * 5;
        bx0 = __ldg(box + 0); bx1 = __ldg(box + 1); bx2 = __ldg(box + 2);
        bx3 = __ldg(box + 3); bx4 = __ldg(box + 4);
        cls = __ldg(gtc + bid);
    }

    // ---- bulk conf term: 1 float4 per thread, streaming (touch-once) ----
    const int chunk = bid >> 4;          // which (b,a), 160 planes
    const int part  = bid & 15;          // sixteenth of the 4096-float plane
    const float4* p = reinterpret_cast<const float4*>(
        out + (size_t)(chunk * CHc + 4) * HWc + part * (HWc / 16));
    float4 v = __ldcs(p + tid);          // evict-first: don't pollute L2

    // ---- per-gt sparse terms ----
    float nll = 0.0f, coord_sq = 0.0f, conf_corr = 0.0f, sl = 0.0f;
    if (has_gt) {
        float gx  = bx0 * (float)Wc;
        float gy  = bx1 * (float)Hc;
        float gw  = bx2 * (float)Wc;
        float gh  = bx3 * (float)Hc;
        float gth = bx4 * 0.39269908169872414f;  // pi/8

        int best = 0;
        float iou_best = __cosf(0.25f * (gth - c_aa[0]));
        #pragma unroll
        for (int a = 1; a < 5; a++) {
            float t = __cosf(0.25f * (gth - c_aa[a]));
            if (t > iou_best) { iou_best = t; best = a; }
        }

        int gi = min(max((int)gx, 0), Wc - 1);
        int gj = min(max((int)gy, 0), Hc - 1);
        int cell = gj * Wc + gi;
        const float* bp = out + (size_t)((bid / Gc) * Ac + best) * CHc * HWc + cell;

        // warp-cooperative log-softmax over 80 class channels (stride HWc)
        float x0 = __ldg(bp + (size_t)(6 + lane) * HWc);
        float x1 = __ldg(bp + (size_t)(6 + lane + 32) * HWc);
        float x2 = (lane < 16) ? __ldg(bp + (size_t)(6 + lane + 64) * HWc) : -INFINITY;
        float e0 = 0.f, e1 = 0.f, e2 = 0.f, e3 = 0.f, e4 = 0.f, e5 = 0.f, exc = 0.f;
        if (lane == 0) {   // issued in parallel with the shuffle chains
            e0 = __ldg(bp + 0 * (size_t)HWc);
            e1 = __ldg(bp + 1 * (size_t)HWc);
            e2 = __ldg(bp + 2 * (size_t)HWc);
            e3 = __ldg(bp + 3 * (size_t)HWc);
            e4 = __ldg(bp + 4 * (size_t)HWc);
            e5 = __ldg(bp + 5 * (size_t)HWc);
            exc = __ldg(bp + (size_t)(6 + cls) * HWc);
        }
        float m = fmaxf(fmaxf(x0, x1), x2);
        #pragma unroll
        for (int off = 16; off > 0; off >>= 1)
            m = fmaxf(m, __shfl_xor_sync(0xffffffffu, m, off));
        float e = __expf(x0 - m) + __expf(x1 - m) + ((lane < 16) ? __expf(x2 - m) : 0.0f);
        #pragma unroll
        for (int off = 16; off > 0; off >>= 1)
            e += __shfl_xor_sync(0xffffffffu, e, off);
        float lse = m + __logf(e);

        if (lane == 0) {
            nll = lse - exc;

            float tx  = gx - (float)gi;
            float ty  = gy - (float)gj;
            float tw  = __logf(fmaxf(gw, 1.0f) / c_aw[best]);
            float th  = __logf(fmaxf(gh, 1.0f) / c_ah[best]);
            float tth = gth - c_aa[best];

            float c0 = sigf(e0), c1 = sigf(e1);
            float d0 = c0 - tx, d1 = c1 - ty, d2 = e2 - tw, d3 = e3 - th;
            coord_sq = d0 * d0 + d1 * d1 + d2 * d2 + d3 * d3;

            float cf = sigf(e4);
            float dc = cf - iou_best;
            conf_corr = 25.0f * dc * dc - cf * cf;

            float d = fabsf(e5 - tth);
            sl = (d < 1.0f) ? 0.5f * d * d : d - 0.5f;
        }
    }

    // ---- per-warp reduce of bulk sigmoid^2 (+ conf correction on gt lane0) ----
    float a0 = sigf(v.x), b0 = sigf(v.y), c0 = sigf(v.z), d0 = sigf(v.w);
    float s = a0 * a0 + b0 * b0 + c0 * c0 + d0 * d0 + conf_corr;
    #pragma unroll
    for (int off = 16; off > 0; off >>= 1)
        s += __shfl_xor_sync(0xffffffffu, s, off);

    // ---- fire-and-forget REDs (32-way address spread), nothing else ----
    float* slot = reinterpret_cast<float*>(&g_slot[(bid * 2 + wid) & 31]);
    if (lane == 0) {
        atomicAdd(slot + 0, s);
        if (has_gt) {
            atomicAdd(slot + 1, coord_sq);
            atomicAdd(slot + 2, nll);
            atomicAdd(slot + 3, sl);
        }
    }
}

__global__ void k_finalize(float* __restrict__ o) {
    const int lane = threadIdx.x;
    float4 v = g_slot[lane];
    float t0 = v.x, t1 = v.y, t2 = v.z, t3 = v.w;
    #pragma unroll
    for (int off = 16; off > 0; off >>= 1) {
        t0 += __shfl_xor_sync(0xffffffffu, t0, off);
        t1 += __shfl_xor_sync(0xffffffffu, t1, off);
        t2 += __shfl_xor_sync(0xffffffffu, t2, off);
        t3 += __shfl_xor_sync(0xffffffffu, t3, off);
    }
    if (lane == 0) {
        const float n = (float)(Bc * Gc);  // 512 distinct obj cells (per-batch permutation)
        float loss_conf  = t0 / (float)((size_t)Bc * Ac * HWc);
        float loss_coord = 5.0f * t1 / (float)((size_t)Bc * Ac * 4 * HWc);
        float loss_cls   = 2.0f * t2 / n;
        float loss_theta = 5.0f * t3 / n;
        o[0] = loss_coord + loss_conf + loss_cls + loss_theta;
        o[1] = loss_coord;
        o[2] = loss_conf;
        o[3] = loss_cls;
        o[4] = loss_theta;
    }
    g_slot[lane] = make_float4(0.f, 0.f, 0.f, 0.f);  // reset for next replay
}

extern "C" void kernel_launch(void* const* d_in, const int* in_sizes, int n_in,
                              void* d_out, int out_size) {
    const float* out = (const float*)d_in[0];
    const float* gtb = (const float*)d_in[1];
    const int*   gtc = (const int*)d_in[2];
    float* o = (float*)d_out;
    k_main<<<NBLK, 64>>>(out, gtb, gtc);
    k_finalize<<<1, 32>>>(o);
}

// round 16
// speedup vs baseline: 1.0652x; 1.0652x over previous
#include <cuda_runtime.h>
#include <math.h>

#define Bc 32
#define Ac 5
#define Hc 64
#define Wc 64
#define HWc 4096
#define Gc 16
#define NCLS 80
#define CHc 86
#define SPLIT 16
#define NBLK (Bc * Ac * SPLIT)   // 2560 blocks x 64 threads, 1 float4/thread

// 32 spread accumulator slots: x=conf sq-sum, y=coord, z=cls nll, w=theta.
// Zero at module load; finalize kernel resets after reading (graph-replay safe).
__device__ float4 g_slot[32];

__constant__ float c_aw[5] = {1.3221f, 3.19275f, 5.05587f, 9.47112f, 11.2364f};
__constant__ float c_ah[5] = {1.73145f, 4.00944f, 8.09892f, 4.84053f, 10.0071f};
__constant__ float c_aa[5] = {0.0f, 0.3927f, 0.7854f, 1.1781f, 1.5708f};

__device__ __forceinline__ float sigf(float x) {
    return __fdividef(1.0f, 1.0f + __expf(-x));
}

__global__ __launch_bounds__(64) void k_main(const float* __restrict__ out,
                                             const float* __restrict__ gtb,
                                             const int* __restrict__ gtc) {
    const int tid  = threadIdx.x;
    const int lane = tid & 31;
    const int wid  = tid >> 5;          // 0 or 1
    const int bid  = blockIdx.x;

    // ---- per-gt inputs first: start the dependent chain early (blocks 0..511, warp 0) ----
    const bool has_gt = (bid < Bc * Gc) && (wid == 0);
    float bx0 = 0.f, bx1 = 0.f, bx2 = 0.f, bx3 = 0.f, bx4 = 0.f;
    int cls = 0;
    if (has_gt) {
        const float* box = gtb + (size_t)bid * 5;
        bx0 = box[0]; bx1 = box[1]; bx2 = box[2]; bx3 = box[3]; bx4 = box[4];
        cls = gtc[bid];
    }

    // ---- bulk conf term: 1 float4 per thread of one (b,a) conf plane sixteenth ----
    const int chunk = bid >> 4;          // which (b,a), 160 planes
    const int part  = bid & 15;          // sixteenth of the 4096-float plane
    const float4* p = reinterpret_cast<const float4*>(
        out + (size_t)(chunk * CHc + 4) * HWc + part * (HWc / 16));
    float4 v = p[tid];

    // ---- per-gt sparse terms ----
    float nll = 0.0f, coord_sq = 0.0f, conf_corr = 0.0f, sl = 0.0f;
    if (has_gt) {
        float gx  = bx0 * (float)Wc;
        float gy  = bx1 * (float)Hc;
        float gw  = bx2 * (float)Wc;
        float gh  = bx3 * (float)Hc;
        float gth = bx4 * 0.39269908169872414f;  // pi/8

        int best = 0;
        float iou_best = __cosf(0.25f * (gth - c_aa[0]));
        #pragma unroll
        for (int a = 1; a < 5; a++) {
            float t = __cosf(0.25f * (gth - c_aa[a]));
            if (t > iou_best) { iou_best = t; best = a; }
        }

        int gi = min(max((int)gx, 0), Wc - 1);
        int gj = min(max((int)gy, 0), Hc - 1);
        int cell = gj * Wc + gi;
        size_t base = (size_t)((bid / Gc) * Ac + best) * CHc * HWc + cell;

        // warp-cooperative log-softmax over 80 class channels (stride HWc)
        float x0 = out[base + (size_t)(6 + lane) * HWc];
        float x1 = out[base + (size_t)(6 + lane + 32) * HWc];
        float x2 = (lane < 16) ? out[base + (size_t)(6 + lane + 64) * HWc] : -INFINITY;
        float e0 = 0.f, e1 = 0.f, e2 = 0.f, e3 = 0.f, e4 = 0.f, e5 = 0.f, exc = 0.f;
        if (lane == 0) {   // issued in parallel with the shuffle chains
            e0 = out[base + 0 * (size_t)HWc];
            e1 = out[base + 1 * (size_t)HWc];
            e2 = out[base + 2 * (size_t)HWc];
            e3 = out[base + 3 * (size_t)HWc];
            e4 = out[base + 4 * (size_t)HWc];
            e5 = out[base + 5 * (size_t)HWc];
            exc = out[base + (size_t)(6 + cls) * HWc];
        }
        float m = fmaxf(fmaxf(x0, x1), x2);
        #pragma unroll
        for (int off = 16; off > 0; off >>= 1)
            m = fmaxf(m, __shfl_xor_sync(0xffffffffu, m, off));
        float e = __expf(x0 - m) + __expf(x1 - m) + ((lane < 16) ? __expf(x2 - m) : 0.0f);
        #pragma unroll
        for (int off = 16; off > 0; off >>= 1)
            e += __shfl_xor_sync(0xffffffffu, e, off);
        float lse = m + __logf(e);

        if (lane == 0) {
            nll = lse - exc;

            float tx  = gx - (float)gi;
            float ty  = gy - (float)gj;
            float tw  = __logf(fmaxf(gw, 1.0f) / c_aw[best]);
            float th  = __logf(fmaxf(gh, 1.0f) / c_ah[best]);
            float tth = gth - c_aa[best];

            float c0 = sigf(e0), c1 = sigf(e1);
            float d0 = c0 - tx, d1 = c1 - ty, d2 = e2 - tw, d3 = e3 - th;
            coord_sq = d0 * d0 + d1 * d1 + d2 * d2 + d3 * d3;

            float cf = sigf(e4);
            float dc = cf - iou_best;
            conf_corr = 25.0f * dc * dc - cf * cf;

            float d = fabsf(e5 - tth);
            sl = (d < 1.0f) ? 0.5f * d * d : d - 0.5f;
        }
    }

    // ---- per-warp reduce of bulk sigmoid^2 (+ conf correction on gt lane0) ----
    float a0 = sigf(v.x), b0 = sigf(v.y), c0 = sigf(v.z), d0 = sigf(v.w);
    float s = a0 * a0 + b0 * b0 + c0 * c0 + d0 * d0 + conf_corr;
    #pragma unroll
    for (int off = 16; off > 0; off >>= 1)
        s += __shfl_xor_sync(0xffffffffu, s, off);

    // ---- fire-and-forget REDs (32-way address spread), nothing else ----
    float* slot = reinterpret_cast<float*>(&g_slot[(bid * 2 + wid) & 31]);
    if (lane == 0) {
        atomicAdd(slot + 0, s);
        if (has_gt) {
            atomicAdd(slot + 1, coord_sq);
            atomicAdd(slot + 2, nll);
            atomicAdd(slot + 3, sl);
        }
    }
}

__global__ void k_finalize(float* __restrict__ o) {
    const int lane = threadIdx.x;
    float4 v = g_slot[lane];
    float t0 = v.x, t1 = v.y, t2 = v.z, t3 = v.w;
    #pragma unroll
    for (int off = 16; off > 0; off >>= 1) {
        t0 += __shfl_xor_sync(0xffffffffu, t0, off);
        t1 += __shfl_xor_sync(0xffffffffu, t1, off);
        t2 += __shfl_xor_sync(0xffffffffu, t2, off);
        t3 += __shfl_xor_sync(0xffffffffu, t3, off);
    }
    if (lane == 0) {
        const float n = (float)(Bc * Gc);  // 512 distinct obj cells (per-batch permutation)
        float loss_conf  = t0 / (float)((size_t)Bc * Ac * HWc);
        float loss_coord = 5.0f * t1 / (float)((size_t)Bc * Ac * 4 * HWc);
        float loss_cls   = 2.0f * t2 / n;
        float loss_theta = 5.0f * t3 / n;
        o[0] = loss_coord + loss_conf + loss_cls + loss_theta;
        o[1] = loss_coord;
        o[2] = loss_conf;
        o[3] = loss_cls;
        o[4] = loss_theta;
    }
    g_slot[lane] = make_float4(0.f, 0.f, 0.f, 0.f);  // reset for next replay
}

extern "C" void kernel_launch(void* const* d_in, const int* in_sizes, int n_in,
                              void* d_out, int out_size) {
    const float* out = (const float*)d_in[0];
    const float* gtb = (const float*)d_in[1];
    const int*   gtc = (const int*)d_in[2];
    float* o = (float*)d_out;
    k_main<<<NBLK, 64>>>(out, gtb, gtc);
    k_finalize<<<1, 32>>>(o);
}

// round 17
// speedup vs baseline: 1.2610x; 1.1838x over previous
#include <cuda_runtime.h>
#include <math.h>

#define Bc 32
#define Ac 5
#define Hc 64
#define Wc 64
#define HWc 4096
#define Gc 16
#define NCLS 80
#define CHc 86
#define SPLIT 8
#define NBLK (Bc * Ac * SPLIT)   // 1280 blocks x 64 threads, 2 float4/thread (MLP=2)

// 32 spread accumulator slots: x=conf sq-sum, y=coord, z=cls nll, w=theta.
// Zero at module load; finalize kernel resets after reading (graph-replay safe).
__device__ float4 g_slot[32];

__constant__ float c_aw[5] = {1.3221f, 3.19275f, 5.05587f, 9.47112f, 11.2364f};
__constant__ float c_ah[5] = {1.73145f, 4.00944f, 8.09892f, 4.84053f, 10.0071f};
__constant__ float c_aa[5] = {0.0f, 0.3927f, 0.7854f, 1.1781f, 1.5708f};

__device__ __forceinline__ float sigf(float x) {
    return __fdividef(1.0f, 1.0f + __expf(-x));
}

__global__ __launch_bounds__(64) void k_main(const float* __restrict__ out,
                                             const float* __restrict__ gtb,
                                             const int* __restrict__ gtc) {
    const int tid  = threadIdx.x;
    const int lane = tid & 31;
    const int wid  = tid >> 5;          // 0 or 1
    const int bid  = blockIdx.x;

    // ---- per-gt inputs first: start the dependent chain early (blocks 0..511, warp 0) ----
    const bool has_gt = (bid < Bc * Gc) && (wid == 0);
    float bx0 = 0.f, bx1 = 0.f, bx2 = 0.f, bx3 = 0.f, bx4 = 0.f;
    int cls = 0;
    if (has_gt) {
        const float* box = gtb + (size_t)bid * 5;
        bx0 = box[0]; bx1 = box[1]; bx2 = box[2]; bx3 = box[3]; bx4 = box[4];
        cls = gtc[bid];
    }

    // ---- bulk conf term: 2 independent float4 per thread (MLP=2) ----
    const int chunk = bid >> 3;          // which (b,a), 160 planes
    const int part  = bid & 7;           // eighth of the 4096-float plane
    const float4* p = reinterpret_cast<const float4*>(
        out + (size_t)(chunk * CHc + 4) * HWc + part * (HWc / 8));
    float4 v0 = p[tid];                  // both loads in flight together
    float4 v1 = p[tid + 64];

    // ---- per-gt sparse terms ----
    float nll = 0.0f, coord_sq = 0.0f, conf_corr = 0.0f, sl = 0.0f;
    if (has_gt) {
        float gx  = bx0 * (float)Wc;
        float gy  = bx1 * (float)Hc;
        float gw  = bx2 * (float)Wc;
        float gh  = bx3 * (float)Hc;
        float gth = bx4 * 0.39269908169872414f;  // pi/8

        int best = 0;
        float iou_best = __cosf(0.25f * (gth - c_aa[0]));
        #pragma unroll
        for (int a = 1; a < 5; a++) {
            float t = __cosf(0.25f * (gth - c_aa[a]));
            if (t > iou_best) { iou_best = t; best = a; }
        }

        int gi = min(max((int)gx, 0), Wc - 1);
        int gj = min(max((int)gy, 0), Hc - 1);
        int cell = gj * Wc + gi;
        size_t base = (size_t)((bid / Gc) * Ac + best) * CHc * HWc + cell;

        // warp-cooperative log-softmax over 80 class channels (stride HWc)
        float x0 = out[base + (size_t)(6 + lane) * HWc];
        float x1 = out[base + (size_t)(6 + lane + 32) * HWc];
        float x2 = (lane < 16) ? out[base + (size_t)(6 + lane + 64) * HWc] : -INFINITY;
        float e0 = 0.f, e1 = 0.f, e2 = 0.f, e3 = 0.f, e4 = 0.f, e5 = 0.f, exc = 0.f;
        if (lane == 0) {   // issued in parallel with the shuffle chains
            e0 = out[base + 0 * (size_t)HWc];
            e1 = out[base + 1 * (size_t)HWc];
            e2 = out[base + 2 * (size_t)HWc];
            e3 = out[base + 3 * (size_t)HWc];
            e4 = out[base + 4 * (size_t)HWc];
            e5 = out[base + 5 * (size_t)HWc];
            exc = out[base + (size_t)(6 + cls) * HWc];
        }
        float m = fmaxf(fmaxf(x0, x1), x2);
        #pragma unroll
        for (int off = 16; off > 0; off >>= 1)
            m = fmaxf(m, __shfl_xor_sync(0xffffffffu, m, off));
        float e = __expf(x0 - m) + __expf(x1 - m) + ((lane < 16) ? __expf(x2 - m) : 0.0f);
        #pragma unroll
        for (int off = 16; off > 0; off >>= 1)
            e += __shfl_xor_sync(0xffffffffu, e, off);
        float lse = m + __logf(e);

        if (lane == 0) {
            nll = lse - exc;

            float tx  = gx - (float)gi;
            float ty  = gy - (float)gj;
            float tw  = __logf(fmaxf(gw, 1.0f) / c_aw[best]);
            float th  = __logf(fmaxf(gh, 1.0f) / c_ah[best]);
            float tth = gth - c_aa[best];

            float c0 = sigf(e0), c1 = sigf(e1);
            float d0 = c0 - tx, d1 = c1 - ty, d2 = e2 - tw, d3 = e3 - th;
            coord_sq = d0 * d0 + d1 * d1 + d2 * d2 + d3 * d3;

            float cf = sigf(e4);
            float dc = cf - iou_best;
            conf_corr = 25.0f * dc * dc - cf * cf;

            float d = fabsf(e5 - tth);
            sl = (d < 1.0f) ? 0.5f * d * d : d - 0.5f;
        }
    }

    // ---- per-warp reduce of bulk sigmoid^2 (+ conf correction on gt lane0) ----
    float a0 = sigf(v0.x), b0 = sigf(v0.y), c0 = sigf(v0.z), d0 = sigf(v0.w);
    float a1 = sigf(v1.x), b1 = sigf(v1.y), c1 = sigf(v1.z), d1 = sigf(v1.w);
    float s = a0 * a0 + b0 * b0 + c0 * c0 + d0 * d0
            + a1 * a1 + b1 * b1 + c1 * c1 + d1 * d1 + conf_corr;
    #pragma unroll
    for (int off = 16; off > 0; off >>= 1)
        s += __shfl_xor_sync(0xffffffffu, s, off);

    // ---- fire-and-forget REDs (32-way address spread), nothing else ----
    float* slot = reinterpret_cast<float*>(&g_slot[(bid * 2 + wid) & 31]);
    if (lane == 0) {
        atomicAdd(slot + 0, s);
        if (has_gt) {
            atomicAdd(slot + 1, coord_sq);
            atomicAdd(slot + 2, nll);
            atomicAdd(slot + 3, sl);
        }
    }
}

__global__ void k_finalize(float* __restrict__ o) {
    const int lane = threadIdx.x;
    float4 v = g_slot[lane];
    float t0 = v.x, t1 = v.y, t2 = v.z, t3 = v.w;
    #pragma unroll
    for (int off = 16; off > 0; off >>= 1) {
        t0 += __shfl_xor_sync(0xffffffffu, t0, off);
        t1 += __shfl_xor_sync(0xffffffffu, t1, off);
        t2 += __shfl_xor_sync(0xffffffffu, t2, off);
        t3 += __shfl_xor_sync(0xffffffffu, t3, off);
    }
    if (lane == 0) {
        const float n = (float)(Bc * Gc);  // 512 distinct obj cells (per-batch permutation)
        float loss_conf  = t0 / (float)((size_t)Bc * Ac * HWc);
        float loss_coord = 5.0f * t1 / (float)((size_t)Bc * Ac * 4 * HWc);
        float loss_cls   = 2.0f * t2 / n;
        float loss_theta = 5.0f * t3 / n;
        o[0] = loss_coord + loss_conf + loss_cls + loss_theta;
        o[1] = loss_coord;
        o[2] = loss_conf;
        o[3] = loss_cls;
        o[4] = loss_theta;
    }
    g_slot[lane] = make_float4(0.f, 0.f, 0.f, 0.f);  // reset for next replay
}

extern "C" void kernel_launch(void* const* d_in, const int* in_sizes, int n_in,
                              void* d_out, int out_size) {
    const float* out = (const float*)d_in[0];
    const float* gtb = (const float*)d_in[1];
    const int*   gtc = (const int*)d_in[2];
    float* o = (float*)d_out;
    k_main<<<NBLK, 64>>>(out, gtb, gtc);
    k_finalize<<<1, 32>>>(o);
}